// round 11
// baseline (speedup 1.0000x reference)
#include <cuda_runtime.h>
#include <math.h>

#define KW   9
#define PAD  4
#define BX   64            // threads in x == tile width (PXT=1)
#define BY   4             // threads in y == tile height
#define TW   64
#define TH   4
#define SXU  (TW + 2*PAD)  // 72 used smem cols
#define SXP  80            // padded smem row stride
#define SY   (TH + 2*PAD)  // 12 smem rows
#define HH   256
#define WW   256
#define CC   3
#define NV4  18            // float4 cols covering SXU
#define NPRE (CC*4*TH*NV4) // 864 pre-add float4 ops

#define INV_DIAG (1.0f / 362.03867196751236f)
#define SIGMA_MIN 0.5f
#define SIGMA_RANGE 9.5f
#define PI_F 3.14159265358979323846f

// rows 0..4 of the symmetric 9x9 q-index map (row oy == row 8-oy)
__device__ constexpr int QIDX5[5][9] = {
    {14,13,12,10, 9,10,12,13,14},
    {13,11, 8, 7, 6, 7, 8,11,13},
    {12, 8, 5, 4, 3, 4, 5, 8,12},
    {10, 7, 4, 2, 1, 2, 4, 7,10},
    { 9, 6, 3, 1, 0, 1, 3, 6, 9},
};

__device__ __forceinline__ int reflect_idx(int v) {
    v = (v < 0) ? -v : v;
    return (v >= HH) ? (2 * HH - 2 - v) : v;   // H == W == 256
}

__device__ __forceinline__ void make_weights(float ddx, float ddy, float* w)
{
    const float d2   = ddx * ddx + ddy * ddy;
    const float dist = sqrtf(d2);
    const float s    = SIGMA_MIN + SIGMA_RANGE * (dist * INV_DIAG);
    const float s2   = s * s;
    const float a    = 0.5f / s2;
    const float common = -dist * sqrtf(s) * __fdividef(1.0f, PI_F * s2 * s2);

    const float E   = __expf(-a);
    const float E2  = E  * E,  E4  = E2  * E2, E5  = E4  * E;
    const float E8  = E4 * E4, E9  = E8  * E,  E10 = E8  * E2;
    const float E13 = E8 * E5, E16 = E8  * E8, E17 = E16 * E;
    const float E18 = E16* E2, E20 = E16 * E4, E25 = E16 * E9;
    const float E32 = E16 * E16;

    w[0]  = common;
    w[1]  = common * fmaf( -1.0f, a, 1.0f) * E;
    w[2]  = common * fmaf( -2.0f, a, 1.0f) * E2;
    w[3]  = common * fmaf( -4.0f, a, 1.0f) * E4;
    w[4]  = common * fmaf( -5.0f, a, 1.0f) * E5;
    w[5]  = common * fmaf( -8.0f, a, 1.0f) * E8;
    w[6]  = common * fmaf( -9.0f, a, 1.0f) * E9;
    w[7]  = common * fmaf(-10.0f, a, 1.0f) * E10;
    w[8]  = common * fmaf(-13.0f, a, 1.0f) * E13;
    w[9]  = common * fmaf(-16.0f, a, 1.0f) * E16;
    w[10] = common * fmaf(-17.0f, a, 1.0f) * E17;
    w[11] = common * fmaf(-18.0f, a, 1.0f) * E18;
    w[12] = common * fmaf(-20.0f, a, 1.0f) * E20;
    w[13] = common * fmaf(-25.0f, a, 1.0f) * E25;
    w[14] = common * fmaf(-32.0f, a, 1.0f) * E32;
}

__global__ __launch_bounds__(BX * BY, 6)
void adaptive_log_conv(const float* __restrict__ x,
                       const float* __restrict__ foa,
                       float* __restrict__ out)
{
    __shared__ __align__(16) float sm[CC][SY][SXP];           // 11.5 KB
    // pr flat-index layout: (((c*4 + a)*TH + row)*NV4 + vc)  -> pow2-friendly decode
    __shared__ __align__(16) float pr[CC][4][TH][SXP];        // 15.4 KB

    const int b   = blockIdx.z;
    const int bx0 = blockIdx.x * TW;
    const int by0 = blockIdx.y * TH;
    const int lx  = threadIdx.x;      // 0..63
    const int ly  = threadIdx.y;      // 0..3
    const int tid = ly * BX + lx;

    const float* xb = x + (size_t)b * CC * HH * WW;

    // ---- tile load: 256 threads, rows {ly, ly+4, ly+8}, cols lx (+ lx+64 for lx<8) ----
    const int gy0 = reflect_idx(by0 + ly     - PAD);
    const int gy1 = reflect_idx(by0 + ly + 4 - PAD);
    const int gy2 = reflect_idx(by0 + ly + 8 - PAD);
    const int gxa = reflect_idx(bx0 + lx      - PAD);
    const int gxb = reflect_idx(bx0 + lx + 64 - PAD);
    const bool hasb = (lx < SXU - 64);     // lx < 8

    #pragma unroll
    for (int c = 0; c < CC; c++) {
        const float* xc = xb + c * (HH * WW);
        const float* r0 = xc + gy0 * WW;
        const float* r1 = xc + gy1 * WW;
        const float* r2 = xc + gy2 * WW;
        sm[c][ly    ][lx] = r0[gxa];
        sm[c][ly + 4][lx] = r1[gxa];
        sm[c][ly + 8][lx] = r2[gxa];
        if (hasb) {
            sm[c][ly    ][lx + 64] = r0[gxb];
            sm[c][ly + 4][lx + 64] = r1[gxb];
            sm[c][ly + 8][lx + 64] = r2[gxb];
        }
    }

    // ---- weight generation: ONE pixel per thread (overlaps in-flight loads) ----
    const int px = bx0 + lx;
    const int py = by0 + ly;
    const float fx  = foa[b * 2 + 0];
    const float fy  = foa[b * 2 + 1];

    float w[15];
    make_weights((float)px - fx, (float)py - fy, w);

    __syncthreads();

    // ---- paired-row pre-add distributed over all 256 threads (864 float4 ops) ----
    #pragma unroll
    for (int k = 0; k < 4; k++) {
        const int i = tid + k * 256;
        if (i < NPRE) {                       // k=3: tid<96 -> warps 0-2 (warp-uniform)
            const int vc  = i % NV4;          // mul-shift, cheap
            const int s   = i / NV4;          // 0..47
            const int row = s & 3;
            const int u   = s >> 2;           // 0..11
            const int a   = u & 3;
            const int c   = u >> 2;
            const float4 p = *(const float4*)&sm[c][row + a    ][4 * vc];
            const float4 q = *(const float4*)&sm[c][row + 8 - a][4 * vc];
            float4 r;
            r.x = p.x + q.x; r.y = p.y + q.y;
            r.z = p.z + q.z; r.w = p.w + q.w;
            *(float4*)&pr[c][a][row][4 * vc] = r;
        }
    }
    __syncthreads();

    // ---- convolution: 5 effective rows x 3 channels, 9 taps each ----
    float acc[CC];
    #pragma unroll
    for (int c = 0; c < CC; c++) acc[c] = 0.0f;

    #pragma unroll
    for (int c = 0; c < CC; c++) {
        #pragma unroll
        for (int a = 0; a < 5; a++) {
            const float* row = (a < 4) ? &pr[c][a][ly][lx]
                                       : &sm[c][ly + 4][lx];
            #pragma unroll
            for (int ox = 0; ox < KW; ox++) {
                acc[c] = fmaf(row[ox], w[QIDX5[a][ox]], acc[c]);
            }
        }
    }

    float* ob = out + (size_t)b * CC * HH * WW;
    #pragma unroll
    for (int c = 0; c < CC; c++)
        ob[(c * HH + py) * WW + px] = acc[c];
}

extern "C" void kernel_launch(void* const* d_in, const int* in_sizes, int n_in,
                              void* d_out, int out_size)
{
    const float* x   = (const float*)d_in[0];
    const float* foa = (const float*)d_in[1];
    float* out = (float*)d_out;

    dim3 block(BX, BY, 1);
    dim3 grid(WW / TW, HH / TH, 4);   // 1024 CTAs x 256 threads = 262144 threads
    adaptive_log_conv<<<grid, block>>>(x, foa, out);
}